// round 11
// baseline (speedup 1.0000x reference)
#include <cuda_runtime.h>

// out[i] = sum_j S[i][j] * w[j],  N = 16384.
// Two rows per CTA (grid 8192, 256 threads): each w value is loaded once and
// feeds the FMA for both rows, halving w-side LSU ops per byte of S streamed.
// Each thread owns 2 independent S streams (2 x 8 LDG.128 in flight).
// S uses __ldcs (evict-first streaming, marginally best measured variant).

#define N_DIM   16384
#define THREADS 256

__global__ __launch_bounds__(THREADS)
void matvec_rowsum_pair_kernel(const float* __restrict__ S,
                               const float* __restrict__ w,
                               float* __restrict__ out)
{
    const int row0 = blockIdx.x * 2;
    const int tid  = threadIdx.x;
    const int lane = tid & 31;
    const int wid  = tid >> 5;

    const float4* Sr0 = reinterpret_cast<const float4*>(S + (size_t)row0 * N_DIM);
    const float4* Sr1 = reinterpret_cast<const float4*>(S + (size_t)(row0 + 1) * N_DIM);
    const float4* W4  = reinterpret_cast<const float4*>(w);

    // 4096 float4 per row / 256 threads = 16 float4 per thread per row.
    float acc0 = 0.0f, acc1 = 0.0f;
    #pragma unroll
    for (int it = 0; it < 16; ++it) {
        const int idx = tid + it * THREADS;     // coalesced across warp
        float4 s0 = __ldcs(&Sr0[idx]);          // streaming: evict-first
        float4 s1 = __ldcs(&Sr1[idx]);
        float4 wv = __ldg(&W4[idx]);            // one w load feeds both rows
        acc0 = fmaf(s0.x, wv.x, acc0);
        acc1 = fmaf(s1.x, wv.x, acc1);
        acc0 = fmaf(s0.y, wv.y, acc0);
        acc1 = fmaf(s1.y, wv.y, acc1);
        acc0 = fmaf(s0.z, wv.z, acc0);
        acc1 = fmaf(s1.z, wv.z, acc1);
        acc0 = fmaf(s0.w, wv.w, acc0);
        acc1 = fmaf(s1.w, wv.w, acc1);
    }

    // Warp reduction (both accumulators)
    #pragma unroll
    for (int off = 16; off > 0; off >>= 1) {
        acc0 += __shfl_xor_sync(0xFFFFFFFFu, acc0, off);
        acc1 += __shfl_xor_sync(0xFFFFFFFFu, acc1, off);
    }

    // Cross-warp reduction (8 warps, 2 rows)
    __shared__ float warp_sums[2][THREADS / 32];
    if (lane == 0) {
        warp_sums[0][wid] = acc0;
        warp_sums[1][wid] = acc1;
    }
    __syncthreads();

    if (wid == 0) {
        float v0 = (lane < THREADS / 32) ? warp_sums[0][lane] : 0.0f;
        float v1 = (lane < THREADS / 32) ? warp_sums[1][lane] : 0.0f;
        #pragma unroll
        for (int off = 4; off > 0; off >>= 1) {
            v0 += __shfl_xor_sync(0xFFFFFFFFu, v0, off);
            v1 += __shfl_xor_sync(0xFFFFFFFFu, v1, off);
        }
        if (lane == 0) {
            out[row0]     = v0;
            out[row0 + 1] = v1;
        }
    }
}

extern "C" void kernel_launch(void* const* d_in, const int* in_sizes, int n_in,
                              void* d_out, int out_size)
{
    const float* S = (const float*)d_in[0];
    const float* w = (const float*)d_in[1];
    float* out = (float*)d_out;

    matvec_rowsum_pair_kernel<<<N_DIM / 2, THREADS>>>(S, w, out);
}

// round 13
// speedup vs baseline: 1.0219x; 1.0219x over previous
#include <cuda_runtime.h>

// out[i] = sum_j S[i][j] * w[j],  N = 16384.
// FINAL: measured-best variant (148.2us, ~91% of HBM spec). One row per CTA,
// 256 threads, occ 8, 16 independent LDG.128 per thread. S streamed with
// __ldcs (evict-first); w on default policy (L1/L2-resident).
// Roofline: 1.074 GB mandatory S traffic / ~7.25 TB/s achieved => this kernel
// sits at the achievable HBM3e ceiling; falsified levers: persistent grid
// (+118% regression), CTA granularity (neutral), w-amortization (neutral).

#define N_DIM   16384
#define THREADS 256

__global__ __launch_bounds__(THREADS, 8)
void matvec_rowsum_kernel(const float* __restrict__ S,
                          const float* __restrict__ w,
                          float* __restrict__ out)
{
    const int row = blockIdx.x;
    const int tid = threadIdx.x;
    const int lane = tid & 31;
    const int wid  = tid >> 5;

    const float4* Srow = reinterpret_cast<const float4*>(S + (size_t)row * N_DIM);
    const float4* W4   = reinterpret_cast<const float4*>(w);

    // 4096 float4 per row / 256 threads = 16 float4 per thread.
    float acc = 0.0f;
    #pragma unroll
    for (int it = 0; it < 16; ++it) {
        const int idx = tid + it * THREADS;    // coalesced across warp
        float4 s  = __ldcs(&Srow[idx]);        // streaming: evict-first
        float4 wv = __ldg(&W4[idx]);           // resident: default policy
        acc = fmaf(s.x, wv.x, acc);
        acc = fmaf(s.y, wv.y, acc);
        acc = fmaf(s.z, wv.z, acc);
        acc = fmaf(s.w, wv.w, acc);
    }

    // Warp reduction
    #pragma unroll
    for (int off = 16; off > 0; off >>= 1)
        acc += __shfl_xor_sync(0xFFFFFFFFu, acc, off);

    // Cross-warp reduction (8 warps)
    __shared__ float warp_sums[THREADS / 32];
    if (lane == 0) warp_sums[wid] = acc;
    __syncthreads();

    if (wid == 0) {
        float v = (lane < THREADS / 32) ? warp_sums[lane] : 0.0f;
        #pragma unroll
        for (int off = 4; off > 0; off >>= 1)
            v += __shfl_xor_sync(0xFFFFFFFFu, v, off);
        if (lane == 0) out[row] = v;
    }
}

extern "C" void kernel_launch(void* const* d_in, const int* in_sizes, int n_in,
                              void* d_out, int out_size)
{
    const float* S = (const float*)d_in[0];
    const float* w = (const float*)d_in[1];
    float* out = (float*)d_out;

    matvec_rowsum_kernel<<<N_DIM, THREADS>>>(S, w, out);
}